// round 15
// baseline (speedup 1.0000x reference)
#include <cuda_runtime.h>
#include <cstdint>

#define N_TOK 32768
#define DDIM 256
#define KSTAGES 8
#define CDSZ 1024

#define TM 32
#define NHALF 8                      // half-chunks of 128 codes
#define KQP 32                       // 32 u64 = 256 int8 k
#define NBLK (N_TOK / TM)            // 1024 main CTAs
#define NBLK_U (N_TOK / 64)          // 512 update CTAs
#define QA_STRIDE 33
#define QCAP 4096
#define SMEM_BYTES (KQP * QA_STRIDE * 8 + 4096 * 8)   // 8448 + 32768 = 41216

typedef unsigned long long u64;

// ------------------------- device scratch (no allocs) -------------------------
__device__ float g_res[N_TOK * DDIM];
__device__ float g_cbT[KSTAGES * DDIM * CDSZ];      // d-major fp32 (fallback)
__device__ float g_cnorm[KSTAGES * CDSZ];
__device__ float g_rnorm[N_TOK];
__device__ float g_sc[KSTAGES * CDSZ];
__device__ u64   g_qb[KSTAGES * NHALF * 4096];      // [stage][half][kqp][4 j][32 tx]
__device__ float g_scmax[KSTAGES];
__device__ float g_cnmax[KSTAGES];
__device__ float g_partials[KSTAGES * NBLK_U];
__device__ int   g_enc[N_TOK];
__device__ int   g_list[N_TOK];
__device__ int   g_acount[KSTAGES];

// ------------------------- helpers -------------------------
__device__ __forceinline__ u64 pack2(float x, float y) {
    u64 r; asm("mov.b64 %0, {%1, %2};" : "=l"(r) : "f"(x), "f"(y)); return r;
}
__device__ __forceinline__ float2 unpack2(u64 v) {
    float2 f; asm("mov.b64 {%0, %1}, %2;" : "=f"(f.x), "=f"(f.y) : "l"(v)); return f;
}
__device__ __forceinline__ u64 fma2(u64 a, u64 b, u64 c) {
    u64 d; asm("fma.rn.f32x2 %0, %1, %2, %3;" : "=l"(d) : "l"(a), "l"(b), "l"(c)); return d;
}
__device__ __forceinline__ int dp4a(int a, int b, int c) {
    int d; asm("dp4a.s32.s32 %0, %1, %2, %3;" : "=r"(d) : "r"(a), "r"(b), "r"(c)); return d;
}
__device__ __forceinline__ uint32_t lo32(u64 v) { return (uint32_t)v; }
__device__ __forceinline__ uint32_t hi32(u64 v) { return (uint32_t)(v >> 32); }
__device__ __forceinline__ uint32_t fflip(float f) {
    uint32_t u = __float_as_uint(f);
    return (u & 0x80000000u) ? ~u : (u | 0x80000000u);
}

// ------------------------- prep -------------------------
__global__ void init_kernel() {
    if (threadIdx.x < KSTAGES) g_acount[threadIdx.x] = 0;
}

__global__ void transpose_cb_kernel(const float* __restrict__ cb) {
    __shared__ float tile[32][33];
    int s = blockIdx.z;
    int d0 = blockIdx.x * 32, c0 = blockIdx.y * 32;
    int tx = threadIdx.x, ty = threadIdx.y;
    const float* src = cb + (size_t)s * CDSZ * DDIM;
    float* dst = g_cbT + (size_t)s * DDIM * CDSZ;
#pragma unroll
    for (int i = 0; i < 32; i += 8)
        tile[ty + i][tx] = src[(size_t)(c0 + ty + i) * DDIM + d0 + tx];
    __syncthreads();
#pragma unroll
    for (int i = 0; i < 32; i += 8)
        dst[(size_t)(d0 + ty + i) * CDSZ + c0 + tx] = tile[tx][ty + i];
}

__global__ void cnorm_kernel(const float* __restrict__ cb) {
    int row = blockIdx.x * 8 + (threadIdx.x >> 5);
    int lane = threadIdx.x & 31;
    int stage = row >> 10;
    const float* p = cb + (size_t)row * DDIM;
    float s = 0.f;
#pragma unroll
    for (int j = 0; j < 8; j++) { float v = p[lane + 32 * j]; s = fmaf(v, v, s); }
#pragma unroll
    for (int off = 16; off; off >>= 1) s += __shfl_xor_sync(0xffffffffu, s, off);
    if (lane == 0) {
        g_cnorm[row] = s;
        atomicMax((int*)&g_cnmax[stage], __float_as_int(s));
    }
}

__global__ void prep_qb_kernel(const float* __restrict__ cb) {
    int row = blockIdx.x * 8 + (threadIdx.x >> 5);
    int lane = threadIdx.x & 31;
    int stage = row >> 10, c = row & 1023;
    const float* p = cb + (size_t)row * DDIM;
    float4 p0 = *(const float4*)&p[lane * 8];
    float4 p1 = *(const float4*)&p[lane * 8 + 4];
    float v[8] = {p0.x, p0.y, p0.z, p0.w, p1.x, p1.y, p1.z, p1.w};
    float m = 0.f;
#pragma unroll
    for (int b = 0; b < 8; b++) m = fmaxf(m, fabsf(v[b]));
#pragma unroll
    for (int off = 16; off; off >>= 1) m = fmaxf(m, __shfl_xor_sync(0xffffffffu, m, off));
    float mm = fmaxf(m, 1e-30f);
    float inv = 127.f / mm;
    int q[8];
#pragma unroll
    for (int b = 0; b < 8; b++) q[b] = __float2int_rn(v[b] * inv);
    uint32_t lo = (q[0] & 0xFF) | ((q[1] & 0xFF) << 8) | ((q[2] & 0xFF) << 16) | ((q[3] & 0xFF) << 24);
    uint32_t hi = (q[4] & 0xFF) | ((q[5] & 0xFF) << 8) | ((q[6] & 0xFF) << 16) | ((q[7] & 0xFF) << 24);
    // [stage][half][kqp=lane][j][tx]; code within half = txc*4 + jc
    int half = c >> 7, cl = c & 127, txc = cl >> 2, jc = cl & 3;
    g_qb[(size_t)(((stage * NHALF + half) * KQP + lane) * 4 + jc) * 32 + txc] =
        (u64)lo | ((u64)hi << 32);
    if (lane == 0) {
        g_sc[row] = mm / 127.f;
        atomicMax((int*)&g_scmax[stage], __float_as_int(mm / 127.f));
    }
}

// ------------------------- main: int8 GEMM + sound candidate queue + exact rescore ----
extern __shared__ u64 dsm_u64[];

__global__ __launch_bounds__(128, 4) void rvq_main_kernel(
    const float* __restrict__ x,
    const float* __restrict__ cball,
    int stage)
{
    u64* qa = dsm_u64;                       // [KQP][33]
    u64* Bs = dsm_u64 + KQP * QA_STRIDE;     // [KQP][4][32] u64
    __shared__ float rnorm_s[TM], sr_s[TM], margin_s[TM];
    __shared__ u64 best_s[TM];
    __shared__ unsigned short queue_s[QCAP];
    __shared__ int qcount_s;

    const int tid = threadIdx.x;
    const int tx = tid & 31, ty = tid >> 5;
    const int tok0 = blockIdx.x * TM;
    const float* src = (stage == 0) ? x : g_res;
    const float* cb = cball + (size_t)stage * CDSZ * DDIM;
    const float scmax = g_scmax[stage];
    const float cnmax = g_cnmax[stage];

    if (tid == 0) qcount_s = 0;
    if (tid < TM) best_s[tid] = ~0ull;

    // ---- phase A: per-token quantize + rnorm (reference chain) + margin ----
#pragma unroll
    for (int i = 0; i < 8; i++) {
        int tg = tok0 + ty * 8 + i;
        const float* p = src + (size_t)tg * DDIM;
        float4 p0 = __ldg((const float4*)&p[tx * 8]);
        float4 p1 = __ldg((const float4*)&p[tx * 8 + 4]);
        float v[8] = {p0.x, p0.y, p0.z, p0.w, p1.x, p1.y, p1.z, p1.w};
        float m = 0.f;
#pragma unroll
        for (int b = 0; b < 8; b++) m = fmaxf(m, fabsf(v[b]));
#pragma unroll
        for (int off = 16; off; off >>= 1) m = fmaxf(m, __shfl_xor_sync(0xffffffffu, m, off));
        float s = 0.f;
#pragma unroll
        for (int j = 0; j < 8; j++) { float w = __ldg(&p[tx + 32 * j]); s = fmaf(w, w, s); }
#pragma unroll
        for (int off = 16; off; off >>= 1) s += __shfl_xor_sync(0xffffffffu, s, off);
        float mm = fmaxf(m, 1e-30f);
        float inv = 127.f / mm;
        int q[8];
#pragma unroll
        for (int b = 0; b < 8; b++) q[b] = __float2int_rn(v[b] * inv);
        uint32_t lo = (q[0] & 0xFF) | ((q[1] & 0xFF) << 8) | ((q[2] & 0xFF) << 16) | ((q[3] & 0xFF) << 24);
        uint32_t hi = (q[4] & 0xFF) | ((q[5] & 0xFF) << 8) | ((q[6] & 0xFF) << 16) | ((q[7] & 0xFF) << 24);
        qa[tx * QA_STRIDE + ty * 8 + i] = (u64)lo | ((u64)hi << 32);
        if (tx == 0) {
            int t = ty * 8 + i;
            float srt = mm / 127.f;
            rnorm_s[t] = s;
            sr_s[t] = srt;
            margin_s[t] = 32.f * sqrtf((scmax * scmax * s + srt * srt * cnmax) * (1.f / 12.f));
            g_rnorm[tg] = s;
        }
    }
    __syncthreads();

    float R8[8], M8[8], sr8[8], m_run[8];
#pragma unroll
    for (int i = 0; i < 8; i++) {
        R8[i] = rnorm_s[ty * 8 + i];
        M8[i] = margin_s[ty * 8 + i];
        sr8[i] = sr_s[ty * 8 + i];
        m_run[i] = 3.4e38f;
    }

    for (int hc = 0; hc < NHALF; hc++) {
        __syncthreads();
        const u64* gb = g_qb + (size_t)(stage * NHALF + hc) * 4096;
#pragma unroll
        for (int r = 0; r < 32; r++) Bs[r * 128 + tid] = __ldg(&gb[r * 128 + tid]);
        __syncthreads();

        int acc[8][4];
#pragma unroll
        for (int i = 0; i < 8; i++)
#pragma unroll
            for (int j = 0; j < 4; j++) acc[i][j] = 0;

#pragma unroll 4
        for (int kqp = 0; kqp < KQP; kqp++) {
            u64 a8[8], b4[4];
#pragma unroll
            for (int i = 0; i < 8; i++) a8[i] = qa[kqp * QA_STRIDE + ty * 8 + i];
#pragma unroll
            for (int j = 0; j < 4; j++) b4[j] = Bs[kqp * 128 + j * 32 + tx];
#pragma unroll
            for (int i = 0; i < 8; i++)
#pragma unroll
                for (int j = 0; j < 4; j++) {
                    acc[i][j] = dp4a(lo32(a8[i]), lo32(b4[j]), acc[i][j]);
                    acc[i][j] = dp4a(hi32(a8[i]), hi32(b4[j]), acc[i][j]);
                }
        }

        float sc4[4], cn4[4];
#pragma unroll
        for (int j = 0; j < 4; j++) {
            int c = stage * CDSZ + hc * 128 + tx * 4 + j;
            sc4[j] = __ldg(&g_sc[c]);
            cn4[j] = __ldg(&g_cnorm[c]);
        }

        // step 1: running approx-min per token
#pragma unroll
        for (int i = 0; i < 8; i++) {
            float tmin = 3.4e38f;
#pragma unroll
            for (int j = 0; j < 4; j++) {
                float ad2 = fmaf(-2.f * sr8[i] * sc4[j], (float)acc[i][j], R8[i]) + cn4[j];
                tmin = fminf(tmin, ad2);
            }
#pragma unroll
            for (int off = 16; off; off >>= 1)
                tmin = fminf(tmin, __shfl_xor_sync(0xffffffffu, tmin, off));
            m_run[i] = fminf(m_run[i], tmin);
        }

        // step 2: queue all candidates with ad2 <= m_run + M  (sound: M = 2E)
#pragma unroll
        for (int i = 0; i < 8; i++) {
            float thr = m_run[i] + M8[i];
#pragma unroll
            for (int j = 0; j < 4; j++) {
                float ad2 = fmaf(-2.f * sr8[i] * sc4[j], (float)acc[i][j], R8[i]) + cn4[j];
                if (ad2 <= thr) {
                    int pos = atomicAdd(&qcount_s, 1);
                    if (pos < QCAP) {
                        int code = hc * 128 + tx * 4 + j;
                        queue_s[pos] = (unsigned short)(((ty * 8 + i) << 10) | code);
                    }
                }
            }
        }
    }
    __syncthreads();

    const int qn = qcount_s;
    if (qn > QCAP) {
        if (tid < TM) {
            int p = atomicAdd(&g_acount[stage], 1);
            g_list[p] = tok0 + tid;
        }
        return;
    }

    // exact rescore of queued candidates (reference-matched serial chain)
    for (int e = tid; e < qn; e += 128) {
        unsigned short ent = queue_s[e];
        int t = ent >> 10;
        int code = ent & 1023;
        const float* rp = src + (size_t)(tok0 + t) * DDIM;
        const float* cp = cb + (size_t)code * DDIM;
        float dot = 0.f;
#pragma unroll 8
        for (int k = 0; k < DDIM; k++) dot = fmaf(__ldg(&rp[k]), __ldg(&cp[k]), dot);
        float d2 = __fadd_rn(__fsub_rn(rnorm_s[t], __fmul_rn(2.0f, dot)),
                             __ldg(&g_cnorm[stage * CDSZ + code]));
        u64 key = ((u64)fflip(d2) << 32) | (uint32_t)code;
        atomicMin(&best_s[t], key);
    }
    __syncthreads();

    if (tid < TM) g_enc[tok0 + tid] = (int)(uint32_t)best_s[tid];
}

// ------------------------- exact full-scan fallback (proven chain) --------------
__global__ __launch_bounds__(256) void fallback_kernel(const float* __restrict__ x, int stage) {
    const float* src = (stage == 0) ? x : g_res;
    const float* cbT = g_cbT + (size_t)stage * DDIM * CDSZ;
    const float* cn = g_cnorm + stage * CDSZ;
    int lane = threadIdx.x & 31;
    int gw = (blockIdx.x * blockDim.x + threadIdx.x) >> 5;
    int nw = (gridDim.x * blockDim.x) >> 5;
    int count = g_acount[stage];
    for (int li = gw; li < count; li += nw) {
        int t = g_list[li];
        const float* r = src + (size_t)t * DDIM;
        float R = g_rnorm[t];
        float bv = 3.4e38f; int bi = 0;
        for (int jb = 0; jb < 4; jb++) {
            u64 acc[4] = {0ull, 0ull, 0ull, 0ull};
            int cbase = lane + 256 * jb;
            for (int k = 0; k < DDIM; k++) {
                float rv = __ldg(&r[k]);
                u64 rp = pack2(rv, rv);
                const float* row = cbT + (size_t)k * CDSZ;
#pragma unroll
                for (int p = 0; p < 4; p++) {
                    int c1 = cbase + 64 * p;
                    acc[p] = fma2(rp, pack2(__ldg(&row[c1]), __ldg(&row[c1 + 32])), acc[p]);
                }
            }
#pragma unroll
            for (int p = 0; p < 4; p++) {
                float2 f = unpack2(acc[p]);
                int c1 = cbase + 64 * p;
                float d2x = __fadd_rn(__fsub_rn(R, __fmul_rn(2.0f, f.x)), __ldg(&cn[c1]));
                float d2y = __fadd_rn(__fsub_rn(R, __fmul_rn(2.0f, f.y)), __ldg(&cn[c1 + 32]));
                if (d2x < bv) { bv = d2x; bi = c1; }
                if (d2y < bv) { bv = d2y; bi = c1 + 32; }
            }
        }
#pragma unroll
        for (int off = 16; off; off >>= 1) {
            float ov = __shfl_xor_sync(0xffffffffu, bv, off);
            int oi = __shfl_xor_sync(0xffffffffu, bi, off);
            if (ov < bv || (ov == bv && oi < bi)) { bv = ov; bi = oi; }
        }
        if (lane == 0) g_enc[t] = bi;
    }
}

// ------------------------- update + stage-7 quant --------------------
__global__ __launch_bounds__(128) void update_kernel(const float* __restrict__ x,
                                                     const float* __restrict__ cb,
                                                     int stage, float* __restrict__ out) {
    __shared__ float wsum[4];
    float* encf = out + 2;
    float* quant = out + 2 + (size_t)N_TOK * KSTAGES;
    const float* src = (stage == 0) ? x : g_res;
    const int tid = threadIdx.x;
    const int warpId = tid >> 5, lane = tid & 31;
    const int tok0 = blockIdx.x * 64;
    float lsum = 0.f;
    for (int t = warpId; t < 64; t += 4) {
        int token = tok0 + t;
        int e = g_enc[token];
        const float* crow = cb + (size_t)e * DDIM;
#pragma unroll
        for (int jj = 0; jj < 8; jj++) {
            int d = lane + jj * 32;
            float r = __ldg(&src[(size_t)token * DDIM + d]);
            float c = __ldg(&crow[d]);
            float nr = r - c;
            g_res[(size_t)token * DDIM + d] = nr;
            if (stage == KSTAGES - 1)
                quant[(size_t)token * DDIM + d] = __ldg(&x[(size_t)token * DDIM + d]) - nr;
            lsum = fmaf(nr, nr, lsum);
        }
        if (lane == 0) encf[(size_t)token * KSTAGES + stage] = (float)e;
    }
#pragma unroll
    for (int off = 16; off; off >>= 1) lsum += __shfl_xor_sync(0xffffffffu, lsum, off);
    if (lane == 0) wsum[warpId] = lsum;
    __syncthreads();
    if (tid == 0)
        g_partials[stage * NBLK_U + blockIdx.x] = wsum[0] + wsum[1] + wsum[2] + wsum[3];
}

// ------------------------- epilogue -------------------------
__global__ void finalize_kernel(float* __restrict__ out) {
    __shared__ float sh[256];
    int tid = threadIdx.x;
    float s = 0.f;
    for (int i = tid; i < KSTAGES * NBLK_U; i += 256) s += g_partials[i];
    sh[tid] = s;
    __syncthreads();
    for (int off = 128; off; off >>= 1) {
        if (tid < off) sh[tid] += sh[tid + off];
        __syncthreads();
    }
    if (tid == 0) {
        float loss = sh[0] * (1.0f / (float)((size_t)N_TOK * DDIM));
        out[0] = loss;
        out[1] = loss;
    }
}

// ------------------------- launch -------------------------
extern "C" void kernel_launch(void* const* d_in, const int* in_sizes, int n_in,
                              void* d_out, int out_size) {
    const float* x  = (const float*)d_in[0];
    const float* cb = (const float*)d_in[1];
    if (n_in >= 2 && in_sizes[0] == KSTAGES * CDSZ * DDIM && in_sizes[1] == N_TOK * DDIM) {
        const float* t = x; x = cb; cb = t;
    }
    float* out = (float*)d_out;

    cudaFuncSetAttribute(rvq_main_kernel,
                         cudaFuncAttributeMaxDynamicSharedMemorySize, SMEM_BYTES);

    init_kernel<<<1, 32>>>();
    transpose_cb_kernel<<<dim3(8, 32, 8), dim3(32, 8)>>>(cb);
    cnorm_kernel<<<(KSTAGES * CDSZ) / 8, 256>>>(cb);
    prep_qb_kernel<<<(KSTAGES * CDSZ) / 8, 256>>>(cb);

    for (int s = 0; s < KSTAGES; s++) {
        rvq_main_kernel<<<NBLK, 128, SMEM_BYTES>>>(x, cb, s);
        fallback_kernel<<<128, 256>>>(x, s);
        update_kernel<<<NBLK_U, 128>>>(x, cb + (size_t)s * CDSZ * DDIM, s, out);
    }

    finalize_kernel<<<1, 256>>>(out);
}

// round 17
// speedup vs baseline: 1.0006x; 1.0006x over previous
#include <cuda_runtime.h>
#include <cstdint>

#define N_TOK 32768
#define DDIM 256
#define KSTAGES 8
#define CDSZ 1024

#define TM 64
#define NCHUNK 4
#define KQP 32                       // 32 u64 = 256 int8 k
#define NBLK (N_TOK / TM)            // 512 main CTAs
#define NBLK_U (N_TOK / 64)          // 512 update CTAs
#define QA_STRIDE 65
#define QCAP 4096
#define SMEM_BYTES (KQP * QA_STRIDE * 8 + 8192 * 8)   // 16640 + 65536 = 82176

typedef unsigned long long u64;

// ------------------------- device scratch (no allocs) -------------------------
__device__ float g_res[N_TOK * DDIM];
__device__ float g_cbT[KSTAGES * DDIM * CDSZ];      // d-major fp32 (fallback)
__device__ float g_cnorm[KSTAGES * CDSZ];
__device__ float g_rnorm[N_TOK];
__device__ float g_sc[KSTAGES * CDSZ];
__device__ u64   g_qb[KSTAGES * NCHUNK * 8192];     // [stage][chunk][kqp][8 j][32 tx]
__device__ float g_scmax[KSTAGES];
__device__ float g_cnmax[KSTAGES];
__device__ float g_partials[KSTAGES * NBLK_U];
__device__ int   g_enc[N_TOK];
__device__ int   g_list[N_TOK];
__device__ int   g_acount[KSTAGES];

// ------------------------- helpers -------------------------
__device__ __forceinline__ u64 pack2(float x, float y) {
    u64 r; asm("mov.b64 %0, {%1, %2};" : "=l"(r) : "f"(x), "f"(y)); return r;
}
__device__ __forceinline__ float2 unpack2(u64 v) {
    float2 f; asm("mov.b64 {%0, %1}, %2;" : "=f"(f.x), "=f"(f.y) : "l"(v)); return f;
}
__device__ __forceinline__ u64 fma2(u64 a, u64 b, u64 c) {
    u64 d; asm("fma.rn.f32x2 %0, %1, %2, %3;" : "=l"(d) : "l"(a), "l"(b), "l"(c)); return d;
}
__device__ __forceinline__ int dp4a(int a, int b, int c) {
    int d; asm("dp4a.s32.s32 %0, %1, %2, %3;" : "=r"(d) : "r"(a), "r"(b), "r"(c)); return d;
}
__device__ __forceinline__ uint32_t lo32(u64 v) { return (uint32_t)v; }
__device__ __forceinline__ uint32_t hi32(u64 v) { return (uint32_t)(v >> 32); }
__device__ __forceinline__ uint32_t fflip(float f) {
    uint32_t u = __float_as_uint(f);
    return (u & 0x80000000u) ? ~u : (u | 0x80000000u);
}

// ------------------------- prep -------------------------
__global__ void init_kernel() {
    if (threadIdx.x < KSTAGES) g_acount[threadIdx.x] = 0;
}

__global__ void transpose_cb_kernel(const float* __restrict__ cb) {
    __shared__ float tile[32][33];
    int s = blockIdx.z;
    int d0 = blockIdx.x * 32, c0 = blockIdx.y * 32;
    int tx = threadIdx.x, ty = threadIdx.y;
    const float* src = cb + (size_t)s * CDSZ * DDIM;
    float* dst = g_cbT + (size_t)s * DDIM * CDSZ;
#pragma unroll
    for (int i = 0; i < 32; i += 8)
        tile[ty + i][tx] = src[(size_t)(c0 + ty + i) * DDIM + d0 + tx];
    __syncthreads();
#pragma unroll
    for (int i = 0; i < 32; i += 8)
        dst[(size_t)(d0 + ty + i) * CDSZ + c0 + tx] = tile[tx][ty + i];
}

__global__ void cnorm_kernel(const float* __restrict__ cb) {
    int row = blockIdx.x * 8 + (threadIdx.x >> 5);
    int lane = threadIdx.x & 31;
    int stage = row >> 10;
    const float* p = cb + (size_t)row * DDIM;
    float s = 0.f;
#pragma unroll
    for (int j = 0; j < 8; j++) { float v = p[lane + 32 * j]; s = fmaf(v, v, s); }
#pragma unroll
    for (int off = 16; off; off >>= 1) s += __shfl_xor_sync(0xffffffffu, s, off);
    if (lane == 0) {
        g_cnorm[row] = s;
        atomicMax((int*)&g_cnmax[stage], __float_as_int(s));
    }
}

__global__ void prep_qb_kernel(const float* __restrict__ cb) {
    int row = blockIdx.x * 8 + (threadIdx.x >> 5);
    int lane = threadIdx.x & 31;
    int stage = row >> 10, c = row & 1023;
    const float* p = cb + (size_t)row * DDIM;
    float4 p0 = *(const float4*)&p[lane * 8];
    float4 p1 = *(const float4*)&p[lane * 8 + 4];
    float v[8] = {p0.x, p0.y, p0.z, p0.w, p1.x, p1.y, p1.z, p1.w};
    float m = 0.f;
#pragma unroll
    for (int b = 0; b < 8; b++) m = fmaxf(m, fabsf(v[b]));
#pragma unroll
    for (int off = 16; off; off >>= 1) m = fmaxf(m, __shfl_xor_sync(0xffffffffu, m, off));
    float mm = fmaxf(m, 1e-30f);
    float inv = 127.f / mm;
    int q[8];
#pragma unroll
    for (int b = 0; b < 8; b++) q[b] = __float2int_rn(v[b] * inv);
    uint32_t lo = (q[0] & 0xFF) | ((q[1] & 0xFF) << 8) | ((q[2] & 0xFF) << 16) | ((q[3] & 0xFF) << 24);
    uint32_t hi = (q[4] & 0xFF) | ((q[5] & 0xFF) << 8) | ((q[6] & 0xFF) << 16) | ((q[7] & 0xFF) << 24);
    int chunk = c >> 8, cl = c & 255, txc = cl >> 3, jc = cl & 7;
    g_qb[(size_t)(((stage * NCHUNK + chunk) * KQP + lane) * 8 + jc) * 32 + txc] =
        (u64)lo | ((u64)hi << 32);
    if (lane == 0) {
        g_sc[row] = mm / 127.f;
        atomicMax((int*)&g_scmax[stage], __float_as_int(mm / 127.f));
    }
}

// ------------------------- main: int8 GEMM + sound candidate queue + exact rescore ----
extern __shared__ u64 dsm_u64[];

__global__ __launch_bounds__(256, 2) void rvq_main_kernel(
    const float* __restrict__ x,
    const float* __restrict__ cball,
    int stage)
{
    u64* qa = dsm_u64;                       // [32 tx][65] (col = token 0..63)
    u64* Bs = dsm_u64 + KQP * QA_STRIDE;     // [KQP][8 j][32 tx] u64
    __shared__ float rnorm_s[TM], sr_s[TM], margin_s[TM];
    __shared__ u64 best_s[TM];
    __shared__ unsigned short queue_s[QCAP];
    __shared__ int qcount_s;

    const int tid = threadIdx.x;
    const int tx = tid & 31, ty = tid >> 5;   // ty 0..7: warp owns tokens ty*8..ty*8+7
    const int tok0 = blockIdx.x * TM;
    const float* src = (stage == 0) ? x : g_res;
    const float* cb = cball + (size_t)stage * CDSZ * DDIM;
    const float scmax = g_scmax[stage];
    const float cnmax = g_cnmax[stage];

    if (tid == 0) qcount_s = 0;
    if (tid < TM) best_s[tid] = ~0ull;

    // ---- phase A: per-token quantize + rnorm (reference chain) + margin ----
#pragma unroll
    for (int i = 0; i < 8; i++) {
        int tg = tok0 + ty * 8 + i;
        const float* p = src + (size_t)tg * DDIM;
        float4 p0 = __ldg((const float4*)&p[tx * 8]);
        float4 p1 = __ldg((const float4*)&p[tx * 8 + 4]);
        float v[8] = {p0.x, p0.y, p0.z, p0.w, p1.x, p1.y, p1.z, p1.w};
        float m = 0.f;
#pragma unroll
        for (int b = 0; b < 8; b++) m = fmaxf(m, fabsf(v[b]));
#pragma unroll
        for (int off = 16; off; off >>= 1) m = fmaxf(m, __shfl_xor_sync(0xffffffffu, m, off));
        float s = 0.f;
#pragma unroll
        for (int j = 0; j < 8; j++) { float w = __ldg(&p[tx + 32 * j]); s = fmaf(w, w, s); }
#pragma unroll
        for (int off = 16; off; off >>= 1) s += __shfl_xor_sync(0xffffffffu, s, off);
        float mm = fmaxf(m, 1e-30f);
        float inv = 127.f / mm;
        int q[8];
#pragma unroll
        for (int b = 0; b < 8; b++) q[b] = __float2int_rn(v[b] * inv);
        uint32_t lo = (q[0] & 0xFF) | ((q[1] & 0xFF) << 8) | ((q[2] & 0xFF) << 16) | ((q[3] & 0xFF) << 24);
        uint32_t hi = (q[4] & 0xFF) | ((q[5] & 0xFF) << 8) | ((q[6] & 0xFF) << 16) | ((q[7] & 0xFF) << 24);
        qa[(size_t)tx * QA_STRIDE + ty * 8 + i] = (u64)lo | ((u64)hi << 32);
        if (tx == 0) {
            int t = ty * 8 + i;
            float srt = mm / 127.f;
            rnorm_s[t] = s;
            sr_s[t] = srt;
            margin_s[t] = 32.f * sqrtf((scmax * scmax * s + srt * srt * cnmax) * (1.f / 12.f));
            g_rnorm[tg] = s;
        }
    }
    __syncthreads();

    float m_run[8];
#pragma unroll
    for (int i = 0; i < 8; i++) m_run[i] = 3.4e38f;

    for (int chunk = 0; chunk < NCHUNK; chunk++) {
        __syncthreads();
        const u64* gb = g_qb + (size_t)(stage * NCHUNK + chunk) * 8192;
#pragma unroll
        for (int r = 0; r < 32; r++) Bs[r * 256 + tid] = __ldg(&gb[r * 256 + tid]);
        __syncthreads();

        int acc[8][8];
#pragma unroll
        for (int i = 0; i < 8; i++)
#pragma unroll
            for (int j = 0; j < 8; j++) acc[i][j] = 0;

#pragma unroll 4
        for (int kqp = 0; kqp < KQP; kqp++) {
            u64 a8[8], b8[8];
#pragma unroll
            for (int i = 0; i < 8; i++) a8[i] = qa[kqp * QA_STRIDE + ty * 8 + i];  // broadcast read
#pragma unroll
            for (int j = 0; j < 8; j++) b8[j] = Bs[kqp * 256 + j * 32 + tx];
#pragma unroll
            for (int i = 0; i < 8; i++)
#pragma unroll
                for (int j = 0; j < 8; j++) {
                    acc[i][j] = dp4a(lo32(a8[i]), lo32(b8[j]), acc[i][j]);
                    acc[i][j] = dp4a(hi32(a8[i]), hi32(b8[j]), acc[i][j]);
                }
        }

        // NOTE: qa is indexed [k-row][token]; a8 reads use kqp as the row. Correct
        // pairing requires qa row = k granule; phase A stored token data at
        // row tx (the k granule that lane quantized). Since lane tx quantized
        // k-bytes [tx*8, tx*8+8), row tx IS k granule tx. Columns are tokens.

        // scales/norms loaded after the hot loop (register-pressure relief)
        float sc8[8], cn8[8];
#pragma unroll
        for (int j = 0; j < 8; j++) {
            int c = stage * CDSZ + chunk * 256 + tx * 8 + j;
            sc8[j] = __ldg(&g_sc[c]);
            cn8[j] = __ldg(&g_cnorm[c]);
        }

        // step 1: running approx-min per token (R/M/sr from smem)
#pragma unroll
        for (int i = 0; i < 8; i++) {
            float R = rnorm_s[ty * 8 + i];
            float sr = sr_s[ty * 8 + i];
            float tmin = 3.4e38f;
#pragma unroll
            for (int j = 0; j < 8; j++) {
                float ad2 = fmaf(-2.f * sr * sc8[j], (float)acc[i][j], R) + cn8[j];
                tmin = fminf(tmin, ad2);
            }
#pragma unroll
            for (int off = 16; off; off >>= 1)
                tmin = fminf(tmin, __shfl_xor_sync(0xffffffffu, tmin, off));
            m_run[i] = fminf(m_run[i], tmin);
        }

        // step 2: queue all candidates with ad2 <= m_run + M  (sound: M = 2E)
#pragma unroll
        for (int i = 0; i < 8; i++) {
            float R = rnorm_s[ty * 8 + i];
            float sr = sr_s[ty * 8 + i];
            float thr = m_run[i] + margin_s[ty * 8 + i];
#pragma unroll
            for (int j = 0; j < 8; j++) {
                float ad2 = fmaf(-2.f * sr * sc8[j], (float)acc[i][j], R) + cn8[j];
                if (ad2 <= thr) {
                    int pos = atomicAdd(&qcount_s, 1);
                    if (pos < QCAP) {
                        int code = chunk * 256 + tx * 8 + j;
                        queue_s[pos] = (unsigned short)(((ty * 8 + i) << 10) | code);
                    }
                }
            }
        }
    }
    __syncthreads();

    const int qn = qcount_s;
    if (qn > QCAP) {
        if (tid < TM) {
            int p = atomicAdd(&g_acount[stage], 1);
            g_list[p] = tok0 + tid;
        }
        return;
    }

    // exact rescore of queued candidates (reference-matched serial chain)
    for (int e = tid; e < qn; e += 256) {
        unsigned short ent = queue_s[e];
        int t = ent >> 10;
        int code = ent & 1023;
        const float* rp = src + (size_t)(tok0 + t) * DDIM;
        const float* cp = cb + (size_t)code * DDIM;
        float dot = 0.f;
#pragma unroll 8
        for (int k = 0; k < DDIM; k++) dot = fmaf(__ldg(&rp[k]), __ldg(&cp[k]), dot);
        float d2 = __fadd_rn(__fsub_rn(rnorm_s[t], __fmul_rn(2.0f, dot)),
                             __ldg(&g_cnorm[stage * CDSZ + code]));
        u64 key = ((u64)fflip(d2) << 32) | (uint32_t)code;
        atomicMin(&best_s[t], key);
    }
    __syncthreads();

    if (tid < TM) g_enc[tok0 + tid] = (int)(uint32_t)best_s[tid];
}

// ------------------------- exact full-scan fallback (proven chain) --------------
__global__ __launch_bounds__(256) void fallback_kernel(const float* __restrict__ x, int stage) {
    const float* src = (stage == 0) ? x : g_res;
    const float* cbT = g_cbT + (size_t)stage * DDIM * CDSZ;
    const float* cn = g_cnorm + stage * CDSZ;
    int lane = threadIdx.x & 31;
    int gw = (blockIdx.x * blockDim.x + threadIdx.x) >> 5;
    int nw = (gridDim.x * blockDim.x) >> 5;
    int count = g_acount[stage];
    for (int li = gw; li < count; li += nw) {
        int t = g_list[li];
        const float* r = src + (size_t)t * DDIM;
        float R = g_rnorm[t];
        float bv = 3.4e38f; int bi = 0;
        for (int jb = 0; jb < 4; jb++) {
            u64 acc[4] = {0ull, 0ull, 0ull, 0ull};
            int cbase = lane + 256 * jb;
            for (int k = 0; k < DDIM; k++) {
                float rv = __ldg(&r[k]);
                u64 rp = pack2(rv, rv);
                const float* row = cbT + (size_t)k * CDSZ;
#pragma unroll
                for (int p = 0; p < 4; p++) {
                    int c1 = cbase + 64 * p;
                    acc[p] = fma2(rp, pack2(__ldg(&row[c1]), __ldg(&row[c1 + 32])), acc[p]);
                }
            }
#pragma unroll
            for (int p = 0; p < 4; p++) {
                float2 f = unpack2(acc[p]);
                int c1 = cbase + 64 * p;
                float d2x = __fadd_rn(__fsub_rn(R, __fmul_rn(2.0f, f.x)), __ldg(&cn[c1]));
                float d2y = __fadd_rn(__fsub_rn(R, __fmul_rn(2.0f, f.y)), __ldg(&cn[c1 + 32]));
                if (d2x < bv) { bv = d2x; bi = c1; }
                if (d2y < bv) { bv = d2y; bi = c1 + 32; }
            }
        }
#pragma unroll
        for (int off = 16; off; off >>= 1) {
            float ov = __shfl_xor_sync(0xffffffffu, bv, off);
            int oi = __shfl_xor_sync(0xffffffffu, bi, off);
            if (ov < bv || (ov == bv && oi < bi)) { bv = ov; bi = oi; }
        }
        if (lane == 0) g_enc[t] = bi;
    }
}

// ------------------------- update + stage-7 quant --------------------
__global__ __launch_bounds__(128) void update_kernel(const float* __restrict__ x,
                                                     const float* __restrict__ cb,
                                                     int stage, float* __restrict__ out) {
    __shared__ float wsum[4];
    float* encf = out + 2;
    float* quant = out + 2 + (size_t)N_TOK * KSTAGES;
    const float* src = (stage == 0) ? x : g_res;
    const int tid = threadIdx.x;
    const int warpId = tid >> 5, lane = tid & 31;
    const int tok0 = blockIdx.x * 64;
    float lsum = 0.f;
    for (int t = warpId; t < 64; t += 4) {
        int token = tok0 + t;
        int e = g_enc[token];
        const float* crow = cb + (size_t)e * DDIM;
#pragma unroll
        for (int jj = 0; jj < 8; jj++) {
            int d = lane + jj * 32;
            float r = __ldg(&src[(size_t)token * DDIM + d]);
            float c = __ldg(&crow[d]);
            float nr = r - c;
            g_res[(size_t)token * DDIM + d] = nr;
            if (stage == KSTAGES - 1)
                quant[(size_t)token * DDIM + d] = __ldg(&x[(size_t)token * DDIM + d]) - nr;
            lsum = fmaf(nr, nr, lsum);
        }
        if (lane == 0) encf[(size_t)token * KSTAGES + stage] = (float)e;
    }
#pragma unroll
    for (int off = 16; off; off >>= 1) lsum += __shfl_xor_sync(0xffffffffu, lsum, off);
    if (lane == 0) wsum[warpId] = lsum;
    __syncthreads();
    if (tid == 0)
        g_partials[stage * NBLK_U + blockIdx.x] = wsum[0] + wsum[1] + wsum[2] + wsum[3];
}

// ------------------------- epilogue -------------------------
__global__ void finalize_kernel(float* __restrict__ out) {
    __shared__ float sh[256];
    int tid = threadIdx.x;
    float s = 0.f;
    for (int i = tid; i < KSTAGES * NBLK_U; i += 256) s += g_partials[i];
    sh[tid] = s;
    __syncthreads();
    for (int off = 128; off; off >>= 1) {
        if (tid < off) sh[tid] += sh[tid + off];
        __syncthreads();
    }
    if (tid == 0) {
        float loss = sh[0] * (1.0f / (float)((size_t)N_TOK * DDIM));
        out[0] = loss;
        out[1] = loss;
    }
}

// ------------------------- launch -------------------------
extern "C" void kernel_launch(void* const* d_in, const int* in_sizes, int n_in,
                              void* d_out, int out_size) {
    const float* x  = (const float*)d_in[0];
    const float* cb = (const float*)d_in[1];
    if (n_in >= 2 && in_sizes[0] == KSTAGES * CDSZ * DDIM && in_sizes[1] == N_TOK * DDIM) {
        const float* t = x; x = cb; cb = t;
    }
    float* out = (float*)d_out;

    cudaFuncSetAttribute(rvq_main_kernel,
                         cudaFuncAttributeMaxDynamicSharedMemorySize, SMEM_BYTES);

    init_kernel<<<1, 32>>>();
    transpose_cb_kernel<<<dim3(8, 32, 8), dim3(32, 8)>>>(cb);
    cnorm_kernel<<<(KSTAGES * CDSZ) / 8, 256>>>(cb);
    prep_qb_kernel<<<(KSTAGES * CDSZ) / 8, 256>>>(cb);

    for (int s = 0; s < KSTAGES; s++) {
        rvq_main_kernel<<<NBLK, 256, SMEM_BYTES>>>(x, cb, s);
        fallback_kernel<<<128, 256>>>(x, s);
        update_kernel<<<NBLK_U, 128>>>(x, cb + (size_t)s * CDSZ * DDIM, s, out);
    }

    finalize_kernel<<<1, 256>>>(out);
}